// round 15
// baseline (speedup 1.0000x reference)
#include <cuda_runtime.h>
#include <cuda_fp16.h>
#include <cstdint>
#include <math.h>

#define SEQ    4096
#define DMODEL 1024
#define NHEAD  16
#define HDIM   64

// ---------------------------------------------------------------------------
// Scratch (__device__ globals; no allocations allowed)
// ---------------------------------------------------------------------------
__device__ __half g_xh[SEQ * DMODEL];
__device__ __half g_Qh[SEQ * DMODEL];
__device__ __half g_Kh[SEQ * DMODEL];
__device__ __half g_Vh[SEQ * DMODEL];
__device__ __half g_Ch[SEQ * DMODEL];
__device__ __half g_WqT[DMODEL * DMODEL];
__device__ __half g_WkT[DMODEL * DMODEL];
__device__ __half g_WvT[DMODEL * DMODEL];
__device__ __half g_WoT[DMODEL * DMODEL];
// split-K partials for heavy q-tiles (global rows 2048..4095)
__device__ float  g_Opart[2][2048 * DMODEL];
__device__ float2 g_ml[2][2048 * NHEAD];
// persistent-CTA work queue counter (zeroed by f2h_kernel each launch)
__device__ int    g_ctr;

#define NITEMS (48 * NHEAD)   // 768 work items

// ---------------------------------------------------------------------------
// PTX helpers (portable sm_80+)
// ---------------------------------------------------------------------------
__device__ __forceinline__ uint32_t smem_u32(const void* p) {
    uint32_t a;
    asm("{ .reg .u64 t; cvta.to.shared.u64 t, %1; cvt.u32.u64 %0, t; }"
        : "=r"(a) : "l"(p));
    return a;
}
#define CP16(s, g) \
    asm volatile("cp.async.cg.shared.global [%0], [%1], 16;" :: "r"(s), "l"(g))
#define CPC() asm volatile("cp.async.commit_group;" ::: "memory")
#define CPW(N) asm volatile("cp.async.wait_group %0;" :: "n"(N) : "memory")

__device__ __forceinline__ void ldm_x4(uint32_t* r, uint32_t addr) {
    asm volatile("ldmatrix.sync.aligned.m8n8.x4.shared.b16 {%0,%1,%2,%3}, [%4];"
                 : "=r"(r[0]), "=r"(r[1]), "=r"(r[2]), "=r"(r[3]) : "r"(addr));
}
__device__ __forceinline__ void ldm_x4_trans(uint32_t* r, uint32_t addr) {
    asm volatile("ldmatrix.sync.aligned.m8n8.x4.trans.shared.b16 {%0,%1,%2,%3}, [%4];"
                 : "=r"(r[0]), "=r"(r[1]), "=r"(r[2]), "=r"(r[3]) : "r"(addr));
}
__device__ __forceinline__ void mma16816(float* d, const uint32_t* a,
                                         uint32_t b0, uint32_t b1) {
    asm volatile(
        "mma.sync.aligned.m16n8k16.row.col.f32.f16.f16.f32 "
        "{%0,%1,%2,%3}, {%4,%5,%6,%7}, {%8,%9}, {%0,%1,%2,%3};"
        : "+f"(d[0]), "+f"(d[1]), "+f"(d[2]), "+f"(d[3])
        : "r"(a[0]), "r"(a[1]), "r"(a[2]), "r"(a[3]), "r"(b0), "r"(b1));
}
__device__ __forceinline__ uint32_t exp2h2(float a, float b) {
    __half2 h = __floats2half2_rn(a, b);
    uint32_t u = *reinterpret_cast<uint32_t*>(&h), r;
    asm("ex2.approx.f16x2 %0, %1;" : "=r"(r) : "r"(u));
    return r;
}
#define HONES 0x3C003C00u   // half2(1.0, 1.0)

// ---------------------------------------------------------------------------
// prep: fp32 -> fp16  (also zeroes the attention work-queue counter)
// ---------------------------------------------------------------------------
__global__ __launch_bounds__(256) void f2h_kernel(
    const float* __restrict__ in, __half* __restrict__ out, int n)
{
    if (blockIdx.x == 0 && threadIdx.x == 0) g_ctr = 0;
    int i = (blockIdx.x * 256 + threadIdx.x) * 4;
    if (i < n) {
        float4 v = *(const float4*)&in[i];
        *(__half2*)&out[i]     = __floats2half2_rn(v.x, v.y);
        *(__half2*)&out[i + 2] = __floats2half2_rn(v.z, v.w);
    }
}

// prep: 4 weights transposed+converted in one launch
struct TW4 { const float* src[4]; __half* dst[4]; float scl[4]; };
__global__ __launch_bounds__(256) void transW4_kernel(TW4 a)
{
    const int z = blockIdx.z;
    const float* in = a.src[z];
    __half* out = a.dst[z];
    const float scale = a.scl[z];
    __shared__ float t[32][33];
    int tx = threadIdx.x, ty = threadIdx.y;
    int x = blockIdx.x * 32 + tx;
    int y = blockIdx.y * 32 + ty;
#pragma unroll
    for (int j = 0; j < 32; j += 8)
        t[ty + j][tx] = in[(size_t)(y + j) * DMODEL + x];
    __syncthreads();
    int nx = blockIdx.x * 32 + ty;
    int kx = blockIdx.y * 32 + tx;
#pragma unroll
    for (int j = 0; j < 32; j += 8)
        out[(size_t)(nx + j) * DMODEL + kx] = __float2half_rn(t[tx][ty + j] * scale);
}

// ---------------------------------------------------------------------------
// GEMM (QKV): C[4096][1024] = A @ Bt^T. CTA 128x128, BK=32, 4 warps (2x2),
// warp tile 64x64. 3-stage cp.async. (round-12 fixed point)
// ---------------------------------------------------------------------------
#define GK  1024
#define BK  32
#define BKP 40      // 80 B pitch
#define NSTG 3

struct QKVArgs { const __half* Wt[3]; __half* Out[3]; };

__global__ __launch_bounds__(128, 3) void gemm_qkv(const __half* __restrict__ A, QKVArgs args)
{
    extern __shared__ char smraw[];
    typedef __half (*Tile)[128][BKP];
    Tile As = (Tile)smraw;
    Tile Bs = (Tile)(smraw + NSTG * 128 * BKP * sizeof(__half));

    const __half* Bt = args.Wt[blockIdx.z];
    __half* outH = args.Out[blockIdx.z];

    const int tid  = threadIdx.x;
    const int lane = tid & 31;
    const int wid  = tid >> 5;
    const int warp_m = wid >> 1;
    const int warp_n = wid & 1;
    const int mbase = blockIdx.y * 128;
    const int nbase = blockIdx.x * 128;

    auto issue = [&](int s, int kt) {
        const int ko = kt * BK;
#pragma unroll
        for (int i = 0; i < 4; i++) {
            int c = tid + i * 128;
            int r = c >> 2, col = (c & 3) * 8;
            CP16(smem_u32(&As[s][r][col]), &A[(size_t)(mbase + r) * GK + ko + col]);
            CP16(smem_u32(&Bs[s][r][col]), &Bt[(size_t)(nbase + r) * GK + ko + col]);
        }
    };

    float acc[4][8][4];
#pragma unroll
    for (int i = 0; i < 4; i++)
#pragma unroll
        for (int j = 0; j < 8; j++)
#pragma unroll
            for (int v = 0; v < 4; v++) acc[i][j][v] = 0.f;

    issue(0, 0); CPC();
    issue(1, 1); CPC();

    const int NK = GK / BK;   // 32
    for (int kt = 0; kt < NK; kt++) {
        const int s = kt % NSTG;
        if (kt + 2 < NK) issue((kt + 2) % NSTG, kt + 2);
        CPC();
        CPW(2);
        __syncthreads();

#pragma unroll
        for (int ks = 0; ks < 2; ks++) {
            const int k0 = ks * 16;
            uint32_t af[4][4];
#pragma unroll
            for (int mt = 0; mt < 4; mt++)
                ldm_x4(af[mt], smem_u32(
                    &As[s][warp_m * 64 + mt * 16 + (lane & 15)][k0 + 8 * (lane >> 4)]));
            uint32_t bf[4][4];
            const int grp = lane >> 3, lr = lane & 7;
#pragma unroll
            for (int nt2 = 0; nt2 < 4; nt2++) {
                int n0 = warp_n * 64 + nt2 * 16;
                ldm_x4(bf[nt2], smem_u32(
                    &Bs[s][n0 + (grp >= 2 ? 8 : 0) + lr][k0 + (grp & 1) * 8]));
            }
#pragma unroll
            for (int mt = 0; mt < 4; mt++)
#pragma unroll
                for (int nt = 0; nt < 8; nt++)
                    mma16816(acc[mt][nt], af[mt],
                             bf[nt >> 1][(nt & 1) * 2], bf[nt >> 1][(nt & 1) * 2 + 1]);
        }
        __syncthreads();
    }

#pragma unroll
    for (int mt = 0; mt < 4; mt++) {
#pragma unroll
        for (int nt = 0; nt < 8; nt++) {
            int r0 = mbase + warp_m * 64 + mt * 16 + (lane >> 2);
            int cc = nbase + warp_n * 64 + nt * 8 + 2 * (lane & 3);
            *(__half2*)&outH[(size_t)r0 * DMODEL + cc] =
                __floats2half2_rn(acc[mt][nt][0], acc[mt][nt][1]);
            *(__half2*)&outH[(size_t)(r0 + 8) * DMODEL + cc] =
                __floats2half2_rn(acc[mt][nt][2], acc[mt][nt][3]);
        }
    }
}

// ---------------------------------------------------------------------------
// GEMM (output): CTA tile 64x128 -> 512 CTAs (full 12-warp/SM residency).
// 4 warps (2x2), warp tile 32x64, BK=32, 3-stage cp.async.
// ---------------------------------------------------------------------------
__global__ __launch_bounds__(128, 3) void gemm_out(
    const __half* __restrict__ A, const __half* __restrict__ Bt,
    const float* __restrict__ bias, float* __restrict__ outF)
{
    extern __shared__ char smraw[];
    typedef __half (*TileA)[64][BKP];
    typedef __half (*TileB)[128][BKP];
    TileA As = (TileA)smraw;
    TileB Bs = (TileB)(smraw + NSTG * 64 * BKP * sizeof(__half));

    const int tid  = threadIdx.x;
    const int lane = tid & 31;
    const int wid  = tid >> 5;
    const int warp_m = wid >> 1;          // 0..1 (32 rows each)
    const int warp_n = wid & 1;           // 0..1 (64 cols each)
    const int mbase = blockIdx.y * 64;
    const int nbase = blockIdx.x * 128;

    // A: 64 rows x 4 chunks = 256 chunks (2/thread); B: 512 chunks (4/thread)
    auto issue = [&](int s, int kt) {
        const int ko = kt * BK;
#pragma unroll
        for (int i = 0; i < 2; i++) {
            int c = tid + i * 128;
            int r = c >> 2, col = (c & 3) * 8;
            CP16(smem_u32(&As[s][r][col]), &A[(size_t)(mbase + r) * GK + ko + col]);
        }
#pragma unroll
        for (int i = 0; i < 4; i++) {
            int c = tid + i * 128;
            int r = c >> 2, col = (c & 3) * 8;
            CP16(smem_u32(&Bs[s][r][col]), &Bt[(size_t)(nbase + r) * GK + ko + col]);
        }
    };

    float acc[2][8][4];
#pragma unroll
    for (int i = 0; i < 2; i++)
#pragma unroll
        for (int j = 0; j < 8; j++)
#pragma unroll
            for (int v = 0; v < 4; v++) acc[i][j][v] = 0.f;

    issue(0, 0); CPC();
    issue(1, 1); CPC();

    const int NK = GK / BK;   // 32
    for (int kt = 0; kt < NK; kt++) {
        const int s = kt % NSTG;
        if (kt + 2 < NK) issue((kt + 2) % NSTG, kt + 2);
        CPC();
        CPW(2);
        __syncthreads();

#pragma unroll
        for (int ks = 0; ks < 2; ks++) {
            const int k0 = ks * 16;
            uint32_t af[2][4];
#pragma unroll
            for (int mt = 0; mt < 2; mt++)
                ldm_x4(af[mt], smem_u32(
                    &As[s][warp_m * 32 + mt * 16 + (lane & 15)][k0 + 8 * (lane >> 4)]));
            uint32_t bf[4][4];
            const int grp = lane >> 3, lr = lane & 7;
#pragma unroll
            for (int nt2 = 0; nt2 < 4; nt2++) {
                int n0 = warp_n * 64 + nt2 * 16;
                ldm_x4(bf[nt2], smem_u32(
                    &Bs[s][n0 + (grp >= 2 ? 8 : 0) + lr][k0 + (grp & 1) * 8]));
            }
#pragma unroll
            for (int mt = 0; mt < 2; mt++)
#pragma unroll
                for (int nt = 0; nt < 8; nt++)
                    mma16816(acc[mt][nt], af[mt],
                             bf[nt >> 1][(nt & 1) * 2], bf[nt >> 1][(nt & 1) * 2 + 1]);
        }
        __syncthreads();
    }

#pragma unroll
    for (int mt = 0; mt < 2; mt++) {
#pragma unroll
        for (int nt = 0; nt < 8; nt++) {
            int r0 = mbase + warp_m * 32 + mt * 16 + (lane >> 2);
            int cc = nbase + warp_n * 64 + nt * 8 + 2 * (lane & 3);
            float2 bv = *(const float2*)&bias[cc];
            *(float2*)&outF[(size_t)r0 * DMODEL + cc] =
                make_float2(acc[mt][nt][0] + bv.x, acc[mt][nt][1] + bv.y);
            *(float2*)&outF[(size_t)(r0 + 8) * DMODEL + cc] =
                make_float2(acc[mt][nt][2] + bv.x, acc[mt][nt][3] + bv.y);
        }
    }
}

// ---------------------------------------------------------------------------
// Flash attention (causal), persistent-CTA dynamic work queue + split-K.
// (round-11/12, unchanged)
// ---------------------------------------------------------------------------
#define APITCH 72

__global__ __launch_bounds__(128, 3) void attn_mma(
    const __half* __restrict__ Qh, const __half* __restrict__ Kh,
    const __half* __restrict__ Vh, __half* __restrict__ Ch)
{
    extern __shared__ char smraw[];
    typedef __half (*QTile)[APITCH];
    QTile Qs = (QTile)smraw;                                       // 128 x 72
    typedef __half (*KTile)[64][APITCH];
    KTile Ks = (KTile)(smraw + 128 * APITCH * sizeof(__half));     // 2 x 64 x 72
    KTile Vs = (KTile)(smraw + (128 + 2 * 64) * APITCH * sizeof(__half));
    int* s_item = (int*)(smraw + (128 + 4 * 64) * APITCH * sizeof(__half));

    const int tid = threadIdx.x, lane = tid & 31, wid = tid >> 5;

    for (;;) {
        if (tid == 0) *s_item = atomicAdd(&g_ctr, 1);
        __syncthreads();
        const int item = *s_item;
        if (item >= NITEMS) break;

        const int w = item >> 4;
        const int h = item & 15;
        int qt, part, kt0, kt1;
        bool split;
        if (w < 32) {
            split = true;
            qt = 31 - (w >> 1);
            part = w & 1;
            int half = qt + 1;                 // k-tiles total = 2qt+2
            kt0 = part ? half : 0;
            kt1 = part ? (2 * qt + 2) : half;
        } else {
            split = false;
            qt = 47 - w;
            part = 0;
            kt0 = 0;
            kt1 = 2 * qt + 2;
        }

        const int qbase = qt * 128;
        const int hcol  = h * HDIM;
        const int m0b = wid * 32;
        const int gm0 = qbase + m0b;

        auto issue_kv = [&](int s, int kt) {
            const int kb = kt * 64;
#pragma unroll
            for (int i = 0; i < 4; i++) {
                int c = tid + i * 128;
                int r = c >> 3, col = (c & 7) * 8;
                CP16(smem_u32(&Ks[s][r][col]), &Kh[(size_t)(kb + r) * DMODEL + hcol + col]);
                CP16(smem_u32(&Vs[s][r][col]), &Vh[(size_t)(kb + r) * DMODEL + hcol + col]);
            }
        };

        issue_kv(0, kt0); CPC();

#pragma unroll
        for (int i = 0; i < 8; i++) {
            int c = tid + i * 128;
            int r = c >> 3, col = (c & 7) * 8;
            *(uint4*)&Qs[r][col] = *(const uint4*)&Qh[(size_t)(qbase + r) * DMODEL + hcol + col];
        }

        float of[2][8][4];
        float mrow[2][2], lrow[2][2];
#pragma unroll
        for (int rf = 0; rf < 2; rf++) {
            mrow[rf][0] = mrow[rf][1] = -1e30f;
            lrow[rf][0] = lrow[rf][1] = 0.f;
#pragma unroll
            for (int j = 0; j < 8; j++)
#pragma unroll
                for (int v = 0; v < 4; v++) of[rf][j][v] = 0.f;
        }

        for (int kt = kt0; kt < kt1; kt++) {
            const int kbase = kt * 64;
            const int s = (kt - kt0) & 1;
            if (kt + 1 < kt1) issue_kv(1 - s, kt + 1);
            CPC();
            CPW(1);
            __syncthreads();

            if (kbase <= gm0 + 31) {
                float sf[2][8][4];
#pragma unroll
                for (int rf = 0; rf < 2; rf++)
#pragma unroll
                    for (int j = 0; j < 8; j++)
#pragma unroll
                        for (int v = 0; v < 4; v++) sf[rf][j][v] = 0.f;

#pragma unroll
                for (int ks = 0; ks < 4; ks++) {
                    const int k0 = ks * 16;
                    uint32_t af[2][4];
#pragma unroll
                    for (int rf = 0; rf < 2; rf++)
                        ldm_x4(af[rf], smem_u32(
                            &Qs[m0b + rf * 16 + (lane & 15)][k0 + 8 * (lane >> 4)]));
                    const int grp = lane >> 3, lr = lane & 7;
#pragma unroll
                    for (int nt2 = 0; nt2 < 4; nt2++) {
                        uint32_t bf[4];
                        ldm_x4(bf, smem_u32(
                            &Ks[s][nt2 * 16 + (grp >= 2 ? 8 : 0) + lr][k0 + (grp & 1) * 8]));
#pragma unroll
                        for (int rf = 0; rf < 2; rf++) {
                            mma16816(sf[rf][nt2 * 2],     af[rf], bf[0], bf[1]);
                            mma16816(sf[rf][nt2 * 2 + 1], af[rf], bf[2], bf[3]);
                        }
                    }
                }

                if (kbase + 63 > gm0) {
#pragma unroll
                    for (int rf = 0; rf < 2; rf++) {
                        int r0g = gm0 + rf * 16 + (lane >> 2), r1g = r0g + 8;
#pragma unroll
                        for (int j = 0; j < 8; j++) {
                            int ng = kbase + 8 * j + 2 * (lane & 3);
                            if (ng > r0g)     sf[rf][j][0] = -1e30f;
                            if (ng + 1 > r0g) sf[rf][j][1] = -1e30f;
                            if (ng > r1g)     sf[rf][j][2] = -1e30f;
                            if (ng + 1 > r1g) sf[rf][j][3] = -1e30f;
                        }
                    }
                }

                uint32_t pa[2][4][4];
#pragma unroll
                for (int rf = 0; rf < 2; rf++) {
                    float rmax0 = -1e30f, rmax1 = -1e30f;
#pragma unroll
                    for (int j = 0; j < 8; j++) {
                        rmax0 = fmaxf(rmax0, fmaxf(sf[rf][j][0], sf[rf][j][1]));
                        rmax1 = fmaxf(rmax1, fmaxf(sf[rf][j][2], sf[rf][j][3]));
                    }
#pragma unroll
                    for (int off = 1; off <= 2; off <<= 1) {
                        rmax0 = fmaxf(rmax0, __shfl_xor_sync(0xffffffffu, rmax0, off));
                        rmax1 = fmaxf(rmax1, __shfl_xor_sync(0xffffffffu, rmax1, off));
                    }
                    float mn0 = fmaxf(mrow[rf][0], rmax0);
                    float mn1 = fmaxf(mrow[rf][1], rmax1);
                    float corr0 = exp2f(mrow[rf][0] - mn0);
                    float corr1 = exp2f(mrow[rf][1] - mn1);
                    mrow[rf][0] = mn0; mrow[rf][1] = mn1;

#pragma unroll
                    for (int j = 0; j < 8; j++) {
                        uint32_t u0 = exp2h2(sf[rf][j][0] - mn0, sf[rf][j][1] - mn0);
                        uint32_t u1 = exp2h2(sf[rf][j][2] - mn1, sf[rf][j][3] - mn1);
                        pa[rf][j >> 1][(j & 1) * 2 + 0] = u0;
                        pa[rf][j >> 1][(j & 1) * 2 + 1] = u1;
                    }

                    float lacc[4] = {0.f, 0.f, 0.f, 0.f};
#pragma unroll
                    for (int t = 0; t < 4; t++)
                        mma16816(lacc, pa[rf][t], HONES, HONES);
                    lrow[rf][0] = lrow[rf][0] * corr0 + lacc[0];
                    lrow[rf][1] = lrow[rf][1] * corr1 + lacc[2];

#pragma unroll
                    for (int j = 0; j < 8; j++) {
                        of[rf][j][0] *= corr0; of[rf][j][1] *= corr0;
                        of[rf][j][2] *= corr1; of[rf][j][3] *= corr1;
                    }
                }

#pragma unroll
                for (int j2 = 0; j2 < 8; j2++) {
#pragma unroll
                    for (int s2 = 0; s2 < 2; s2++) {
                        uint32_t vf[4];
                        ldm_x4_trans(vf, smem_u32(&Vs[s][32 * s2 + lane][8 * j2]));
#pragma unroll
                        for (int rf = 0; rf < 2; rf++) {
                            mma16816(of[rf][j2], pa[rf][2 * s2],     vf[0], vf[1]);
                            mma16816(of[rf][j2], pa[rf][2 * s2 + 1], vf[2], vf[3]);
                        }
                    }
                }
            }
            __syncthreads();
        }

        if (!split) {
#pragma unroll
            for (int rf = 0; rf < 2; rf++) {
                float inv0 = 1.f / lrow[rf][0], inv1 = 1.f / lrow[rf][1];
                int r0 = gm0 + rf * 16 + (lane >> 2), r1 = r0 + 8;
#pragma unroll
                for (int j2 = 0; j2 < 8; j2++) {
                    int cc = hcol + 8 * j2 + 2 * (lane & 3);
                    *(__half2*)&Ch[(size_t)r0 * DMODEL + cc] =
                        __floats2half2_rn(of[rf][j2][0] * inv0, of[rf][j2][1] * inv0);
                    *(__half2*)&Ch[(size_t)r1 * DMODEL + cc] =
                        __floats2half2_rn(of[rf][j2][2] * inv1, of[rf][j2][3] * inv1);
                }
            }
        } else {
            float* Op = g_Opart[part];
            float2* mlp = g_ml[part];
#pragma unroll
            for (int rf = 0; rf < 2; rf++) {
                int r0 = gm0 + rf * 16 + (lane >> 2), r1 = r0 + 8;
                int p0 = r0 - 2048, p1 = r1 - 2048;
#pragma unroll
                for (int j2 = 0; j2 < 8; j2++) {
                    int cc = hcol + 8 * j2 + 2 * (lane & 3);
                    *(float2*)&Op[(size_t)p0 * DMODEL + cc] =
                        make_float2(of[rf][j2][0], of[rf][j2][1]);
                    *(float2*)&Op[(size_t)p1 * DMODEL + cc] =
                        make_float2(of[rf][j2][2], of[rf][j2][3]);
                }
                if ((lane & 3) == 0) {
                    mlp[p0 * NHEAD + h] = make_float2(mrow[rf][0], lrow[rf][0]);
                    mlp[p1 * NHEAD + h] = make_float2(mrow[rf][1], lrow[rf][1]);
                }
            }
        }
    }
}

// ---------------------------------------------------------------------------
// Combine split-K partials for heavy rows -> Ch[2048..4095]
// ---------------------------------------------------------------------------
__global__ __launch_bounds__(256) void attn_combine(__half* __restrict__ Ch)
{
    int idx = blockIdx.x * 256 + threadIdx.x;
    int row = idx >> 9;
    int col2 = idx & 511;
    int h = col2 >> 5;

    float2 ml0 = g_ml[0][row * NHEAD + h];
    float2 ml1 = g_ml[1][row * NHEAD + h];
    float m  = fmaxf(ml0.x, ml1.x);
    float f0 = exp2f(ml0.x - m), f1 = exp2f(ml1.x - m);
    float inv = 1.f / (ml0.y * f0 + ml1.y * f1);

    float2 o0 = *(const float2*)&g_Opart[0][(size_t)row * DMODEL + col2 * 2];
    float2 o1 = *(const float2*)&g_Opart[1][(size_t)row * DMODEL + col2 * 2];
    float a = (o0.x * f0 + o1.x * f1) * inv;
    float b = (o0.y * f0 + o1.y * f1) * inv;
    *(__half2*)&Ch[(size_t)(2048 + row) * DMODEL + col2 * 2] = __floats2half2_rn(a, b);
}

// ---------------------------------------------------------------------------
extern "C" void kernel_launch(void* const* d_in, const int* in_sizes, int n_in,
                              void* d_out, int out_size)
{
    const float* x  = (const float*)d_in[0];
    const float* Wq = (const float*)d_in[1];
    const float* Wk = (const float*)d_in[2];
    const float* Wv = (const float*)d_in[3];
    const float* Wo = (const float*)d_in[4];
    const float* bo = (const float*)d_in[5];
    float* out = (float*)d_out;

    __half *xh, *Qh, *Kh, *Vh, *Chp, *WqT, *WkT, *WvT, *WoT;
    cudaGetSymbolAddress((void**)&xh,  g_xh);
    cudaGetSymbolAddress((void**)&Qh,  g_Qh);
    cudaGetSymbolAddress((void**)&Kh,  g_Kh);
    cudaGetSymbolAddress((void**)&Vh,  g_Vh);
    cudaGetSymbolAddress((void**)&Chp, g_Ch);
    cudaGetSymbolAddress((void**)&WqT, g_WqT);
    cudaGetSymbolAddress((void**)&WkT, g_WkT);
    cudaGetSymbolAddress((void**)&WvT, g_WvT);
    cudaGetSymbolAddress((void**)&WoT, g_WoT);

    f2h_kernel<<<SEQ * DMODEL / 1024, 256>>>(x, xh, SEQ * DMODEL);

    TW4 tw;
    tw.src[0] = Wq;  tw.dst[0] = WqT; tw.scl[0] = 0.125f * 1.44269504089f;
    tw.src[1] = Wk;  tw.dst[1] = WkT; tw.scl[1] = 1.0f;
    tw.src[2] = Wv;  tw.dst[2] = WvT; tw.scl[2] = 1.0f;
    tw.src[3] = Wo;  tw.dst[3] = WoT; tw.scl[3] = 1.0f;
    transW4_kernel<<<dim3(32, 32, 4), dim3(32, 8)>>>(tw);

    const int gsmem  = NSTG * 128 * BKP * 2 * (int)sizeof(__half);        // 61,440 B
    const int gsmem2 = NSTG * (64 + 128) * BKP * (int)sizeof(__half);     // 46,080 B
    cudaFuncSetAttribute(gemm_qkv, cudaFuncAttributeMaxDynamicSharedMemorySize, gsmem);
    cudaFuncSetAttribute(gemm_out, cudaFuncAttributeMaxDynamicSharedMemorySize, gsmem2);

    QKVArgs qa;
    qa.Wt[0] = WqT; qa.Out[0] = Qh;
    qa.Wt[1] = WkT; qa.Out[1] = Kh;
    qa.Wt[2] = WvT; qa.Out[2] = Vh;
    gemm_qkv<<<dim3(DMODEL / 128, SEQ / 128, 3), 128, gsmem>>>(xh, qa);

    const int asmem = (128 + 4 * 64) * APITCH * (int)sizeof(__half) + 16;  // 55,312 B
    cudaFuncSetAttribute(attn_mma, cudaFuncAttributeMaxDynamicSharedMemorySize, asmem);
    attn_mma<<<dim3(444), 128, asmem>>>(Qh, Kh, Vh, Chp);

    attn_combine<<<(2048 * 512) / 256, 256>>>(Chp);

    gemm_out<<<dim3(DMODEL / 128, SEQ / 64), 128, gsmem2>>>(Chp, WoT, bo, out);
}

// round 16
// speedup vs baseline: 1.0601x; 1.0601x over previous
#include <cuda_runtime.h>
#include <cuda_fp16.h>
#include <cstdint>
#include <math.h>

#define SEQ    4096
#define DMODEL 1024
#define NHEAD  16
#define HDIM   64

// ---------------------------------------------------------------------------
// Scratch (__device__ globals; no allocations allowed)
// ---------------------------------------------------------------------------
__device__ __half g_xh[SEQ * DMODEL];
__device__ __half g_Qh[SEQ * DMODEL];
__device__ __half g_Kh[SEQ * DMODEL];
__device__ __half g_Vh[SEQ * DMODEL];
__device__ __half g_Ch[SEQ * DMODEL];
__device__ __half g_WqT[DMODEL * DMODEL];
__device__ __half g_WkT[DMODEL * DMODEL];
__device__ __half g_WvT[DMODEL * DMODEL];
__device__ __half g_WoT[DMODEL * DMODEL];
// split-K partials for heavy q-tiles (global rows 2048..4095)
__device__ float  g_Opart[2][2048 * DMODEL];
__device__ float2 g_ml[2][2048 * NHEAD];
// persistent-CTA work queue counter (zeroed by f2h_kernel each launch)
__device__ int    g_ctr;

#define NITEMS (48 * NHEAD)   // 768 work items

// ---------------------------------------------------------------------------
// PTX helpers (portable sm_80+)
// ---------------------------------------------------------------------------
__device__ __forceinline__ uint32_t smem_u32(const void* p) {
    uint32_t a;
    asm("{ .reg .u64 t; cvta.to.shared.u64 t, %1; cvt.u32.u64 %0, t; }"
        : "=r"(a) : "l"(p));
    return a;
}
#define CP16(s, g) \
    asm volatile("cp.async.cg.shared.global [%0], [%1], 16;" :: "r"(s), "l"(g))
#define CPC() asm volatile("cp.async.commit_group;" ::: "memory")
#define CPW(N) asm volatile("cp.async.wait_group %0;" :: "n"(N) : "memory")

__device__ __forceinline__ void ldm_x4(uint32_t* r, uint32_t addr) {
    asm volatile("ldmatrix.sync.aligned.m8n8.x4.shared.b16 {%0,%1,%2,%3}, [%4];"
                 : "=r"(r[0]), "=r"(r[1]), "=r"(r[2]), "=r"(r[3]) : "r"(addr));
}
__device__ __forceinline__ void ldm_x4_trans(uint32_t* r, uint32_t addr) {
    asm volatile("ldmatrix.sync.aligned.m8n8.x4.trans.shared.b16 {%0,%1,%2,%3}, [%4];"
                 : "=r"(r[0]), "=r"(r[1]), "=r"(r[2]), "=r"(r[3]) : "r"(addr));
}
__device__ __forceinline__ void mma16816(float* d, const uint32_t* a,
                                         uint32_t b0, uint32_t b1) {
    asm volatile(
        "mma.sync.aligned.m16n8k16.row.col.f32.f16.f16.f32 "
        "{%0,%1,%2,%3}, {%4,%5,%6,%7}, {%8,%9}, {%0,%1,%2,%3};"
        : "+f"(d[0]), "+f"(d[1]), "+f"(d[2]), "+f"(d[3])
        : "r"(a[0]), "r"(a[1]), "r"(a[2]), "r"(a[3]), "r"(b0), "r"(b1));
}
__device__ __forceinline__ uint32_t exp2h2(float a, float b) {
    __half2 h = __floats2half2_rn(a, b);
    uint32_t u = *reinterpret_cast<uint32_t*>(&h), r;
    asm("ex2.approx.f16x2 %0, %1;" : "=r"(r) : "r"(u));
    return r;
}
#define HONES 0x3C003C00u   // half2(1.0, 1.0)

// ---------------------------------------------------------------------------
// prep: fp32 -> fp16  (also zeroes the attention work-queue counter)
// ---------------------------------------------------------------------------
__global__ __launch_bounds__(256) void f2h_kernel(
    const float* __restrict__ in, __half* __restrict__ out, int n)
{
    if (blockIdx.x == 0 && threadIdx.x == 0) g_ctr = 0;
    int i = (blockIdx.x * 256 + threadIdx.x) * 4;
    if (i < n) {
        float4 v = *(const float4*)&in[i];
        *(__half2*)&out[i]     = __floats2half2_rn(v.x, v.y);
        *(__half2*)&out[i + 2] = __floats2half2_rn(v.z, v.w);
    }
}

// prep: 4 weights transposed+converted in one launch
struct TW4 { const float* src[4]; __half* dst[4]; float scl[4]; };
__global__ __launch_bounds__(256) void transW4_kernel(TW4 a)
{
    const int z = blockIdx.z;
    const float* in = a.src[z];
    __half* out = a.dst[z];
    const float scale = a.scl[z];
    __shared__ float t[32][33];
    int tx = threadIdx.x, ty = threadIdx.y;
    int x = blockIdx.x * 32 + tx;
    int y = blockIdx.y * 32 + ty;
#pragma unroll
    for (int j = 0; j < 32; j += 8)
        t[ty + j][tx] = in[(size_t)(y + j) * DMODEL + x];
    __syncthreads();
    int nx = blockIdx.x * 32 + ty;
    int kx = blockIdx.y * 32 + tx;
#pragma unroll
    for (int j = 0; j < 32; j += 8)
        out[(size_t)(nx + j) * DMODEL + kx] = __float2half_rn(t[tx][ty + j] * scale);
}

// ---------------------------------------------------------------------------
// GEMM body: C[4096][1024] = A @ Bt^T (+bias). CTA 128x128, BK=32,
// 4 warps (2x2), warp tile 64x64. Templated cp.async stage count.
// ---------------------------------------------------------------------------
#define GK  1024
#define BK  32
#define BKP 40      // 80 B pitch

template <int STAGES>
__device__ __forceinline__ void gemm_body(
    const __half* __restrict__ A, const __half* __restrict__ Bt,
    const float* __restrict__ bias,
    float* __restrict__ outF, __half* __restrict__ outH, char* smraw)
{
    typedef __half (*Tile)[128][BKP];
    Tile As = (Tile)smraw;
    Tile Bs = (Tile)(smraw + STAGES * 128 * BKP * sizeof(__half));

    const int tid  = threadIdx.x;
    const int lane = tid & 31;
    const int wid  = tid >> 5;            // 0..3
    const int warp_m = wid >> 1;          // 0..1
    const int warp_n = wid & 1;           // 0..1
    const int mbase = blockIdx.y * 128;
    const int nbase = blockIdx.x * 128;

    auto issue = [&](int s, int kt) {
        const int ko = kt * BK;
#pragma unroll
        for (int i = 0; i < 4; i++) {
            int c = tid + i * 128;
            int r = c >> 2, col = (c & 3) * 8;
            CP16(smem_u32(&As[s][r][col]), &A[(size_t)(mbase + r) * GK + ko + col]);
            CP16(smem_u32(&Bs[s][r][col]), &Bt[(size_t)(nbase + r) * GK + ko + col]);
        }
    };

    float acc[4][8][4];
#pragma unroll
    for (int i = 0; i < 4; i++)
#pragma unroll
        for (int j = 0; j < 8; j++)
#pragma unroll
            for (int v = 0; v < 4; v++) acc[i][j][v] = 0.f;

#pragma unroll
    for (int p = 0; p < STAGES - 1; p++) { issue(p, p); CPC(); }

    const int NK = GK / BK;   // 32
    for (int kt = 0; kt < NK; kt++) {
        const int s = kt % STAGES;
        if (kt + STAGES - 1 < NK) issue((kt + STAGES - 1) % STAGES, kt + STAGES - 1);
        CPC();
        CPW(STAGES - 1);
        __syncthreads();

#pragma unroll
        for (int ks = 0; ks < 2; ks++) {
            const int k0 = ks * 16;
            uint32_t af[4][4];
#pragma unroll
            for (int mt = 0; mt < 4; mt++)
                ldm_x4(af[mt], smem_u32(
                    &As[s][warp_m * 64 + mt * 16 + (lane & 15)][k0 + 8 * (lane >> 4)]));
            uint32_t bf[4][4];
            const int grp = lane >> 3, lr = lane & 7;
#pragma unroll
            for (int nt2 = 0; nt2 < 4; nt2++) {
                int n0 = warp_n * 64 + nt2 * 16;
                ldm_x4(bf[nt2], smem_u32(
                    &Bs[s][n0 + (grp >= 2 ? 8 : 0) + lr][k0 + (grp & 1) * 8]));
            }
#pragma unroll
            for (int mt = 0; mt < 4; mt++)
#pragma unroll
                for (int nt = 0; nt < 8; nt++)
                    mma16816(acc[mt][nt], af[mt],
                             bf[nt >> 1][(nt & 1) * 2], bf[nt >> 1][(nt & 1) * 2 + 1]);
        }
        __syncthreads();
    }

#pragma unroll
    for (int mt = 0; mt < 4; mt++) {
#pragma unroll
        for (int nt = 0; nt < 8; nt++) {
            int r0 = mbase + warp_m * 64 + mt * 16 + (lane >> 2);
            int cc = nbase + warp_n * 64 + nt * 8 + 2 * (lane & 3);
            float v0 = acc[mt][nt][0], v1 = acc[mt][nt][1];
            float v2 = acc[mt][nt][2], v3 = acc[mt][nt][3];
            if (bias) {
                float2 bv = *(const float2*)&bias[cc];
                v0 += bv.x; v1 += bv.y; v2 += bv.x; v3 += bv.y;
            }
            if (outF) {
                *(float2*)&outF[(size_t)r0 * DMODEL + cc]       = make_float2(v0, v1);
                *(float2*)&outF[(size_t)(r0 + 8) * DMODEL + cc] = make_float2(v2, v3);
            }
            if (outH) {
                *(__half2*)&outH[(size_t)r0 * DMODEL + cc]       = __floats2half2_rn(v0, v1);
                *(__half2*)&outH[(size_t)(r0 + 8) * DMODEL + cc] = __floats2half2_rn(v2, v3);
            }
        }
    }
}

struct QKVArgs { const __half* Wt[3]; __half* Out[3]; };

__global__ __launch_bounds__(128, 3) void gemm_qkv(const __half* __restrict__ A, QKVArgs args)
{
    extern __shared__ char sm[];
    const int z = blockIdx.z;
    gemm_body<3>(A, args.Wt[z], nullptr, nullptr, args.Out[z], sm);
}

__global__ __launch_bounds__(128, 3) void gemm_out(
    const __half* __restrict__ A, const __half* __restrict__ Bt,
    const float* __restrict__ bias, float* __restrict__ outF)
{
    extern __shared__ char sm[];
    gemm_body<4>(A, Bt, bias, outF, nullptr, sm);
}

// ---------------------------------------------------------------------------
// Flash attention (causal), persistent-CTA dynamic work queue + split-K.
// (round-11/12, unchanged)
// ---------------------------------------------------------------------------
#define APITCH 72

__global__ __launch_bounds__(128, 3) void attn_mma(
    const __half* __restrict__ Qh, const __half* __restrict__ Kh,
    const __half* __restrict__ Vh, __half* __restrict__ Ch)
{
    extern __shared__ char smraw[];
    typedef __half (*QTile)[APITCH];
    QTile Qs = (QTile)smraw;                                       // 128 x 72
    typedef __half (*KTile)[64][APITCH];
    KTile Ks = (KTile)(smraw + 128 * APITCH * sizeof(__half));     // 2 x 64 x 72
    KTile Vs = (KTile)(smraw + (128 + 2 * 64) * APITCH * sizeof(__half));
    int* s_item = (int*)(smraw + (128 + 4 * 64) * APITCH * sizeof(__half));

    const int tid = threadIdx.x, lane = tid & 31, wid = tid >> 5;

    for (;;) {
        if (tid == 0) *s_item = atomicAdd(&g_ctr, 1);
        __syncthreads();
        const int item = *s_item;
        if (item >= NITEMS) break;

        const int w = item >> 4;
        const int h = item & 15;
        int qt, part, kt0, kt1;
        bool split;
        if (w < 32) {
            split = true;
            qt = 31 - (w >> 1);
            part = w & 1;
            int half = qt + 1;                 // k-tiles total = 2qt+2
            kt0 = part ? half : 0;
            kt1 = part ? (2 * qt + 2) : half;
        } else {
            split = false;
            qt = 47 - w;
            part = 0;
            kt0 = 0;
            kt1 = 2 * qt + 2;
        }

        const int qbase = qt * 128;
        const int hcol  = h * HDIM;
        const int m0b = wid * 32;
        const int gm0 = qbase + m0b;

        auto issue_kv = [&](int s, int kt) {
            const int kb = kt * 64;
#pragma unroll
            for (int i = 0; i < 4; i++) {
                int c = tid + i * 128;
                int r = c >> 3, col = (c & 7) * 8;
                CP16(smem_u32(&Ks[s][r][col]), &Kh[(size_t)(kb + r) * DMODEL + hcol + col]);
                CP16(smem_u32(&Vs[s][r][col]), &Vh[(size_t)(kb + r) * DMODEL + hcol + col]);
            }
        };

        issue_kv(0, kt0); CPC();

#pragma unroll
        for (int i = 0; i < 8; i++) {
            int c = tid + i * 128;
            int r = c >> 3, col = (c & 7) * 8;
            *(uint4*)&Qs[r][col] = *(const uint4*)&Qh[(size_t)(qbase + r) * DMODEL + hcol + col];
        }

        float of[2][8][4];
        float mrow[2][2], lrow[2][2];
#pragma unroll
        for (int rf = 0; rf < 2; rf++) {
            mrow[rf][0] = mrow[rf][1] = -1e30f;
            lrow[rf][0] = lrow[rf][1] = 0.f;
#pragma unroll
            for (int j = 0; j < 8; j++)
#pragma unroll
                for (int v = 0; v < 4; v++) of[rf][j][v] = 0.f;
        }

        for (int kt = kt0; kt < kt1; kt++) {
            const int kbase = kt * 64;
            const int s = (kt - kt0) & 1;
            if (kt + 1 < kt1) issue_kv(1 - s, kt + 1);
            CPC();
            CPW(1);
            __syncthreads();

            if (kbase <= gm0 + 31) {
                float sf[2][8][4];
#pragma unroll
                for (int rf = 0; rf < 2; rf++)
#pragma unroll
                    for (int j = 0; j < 8; j++)
#pragma unroll
                        for (int v = 0; v < 4; v++) sf[rf][j][v] = 0.f;

#pragma unroll
                for (int ks = 0; ks < 4; ks++) {
                    const int k0 = ks * 16;
                    uint32_t af[2][4];
#pragma unroll
                    for (int rf = 0; rf < 2; rf++)
                        ldm_x4(af[rf], smem_u32(
                            &Qs[m0b + rf * 16 + (lane & 15)][k0 + 8 * (lane >> 4)]));
                    const int grp = lane >> 3, lr = lane & 7;
#pragma unroll
                    for (int nt2 = 0; nt2 < 4; nt2++) {
                        uint32_t bf[4];
                        ldm_x4(bf, smem_u32(
                            &Ks[s][nt2 * 16 + (grp >= 2 ? 8 : 0) + lr][k0 + (grp & 1) * 8]));
#pragma unroll
                        for (int rf = 0; rf < 2; rf++) {
                            mma16816(sf[rf][nt2 * 2],     af[rf], bf[0], bf[1]);
                            mma16816(sf[rf][nt2 * 2 + 1], af[rf], bf[2], bf[3]);
                        }
                    }
                }

                if (kbase + 63 > gm0) {
#pragma unroll
                    for (int rf = 0; rf < 2; rf++) {
                        int r0g = gm0 + rf * 16 + (lane >> 2), r1g = r0g + 8;
#pragma unroll
                        for (int j = 0; j < 8; j++) {
                            int ng = kbase + 8 * j + 2 * (lane & 3);
                            if (ng > r0g)     sf[rf][j][0] = -1e30f;
                            if (ng + 1 > r0g) sf[rf][j][1] = -1e30f;
                            if (ng > r1g)     sf[rf][j][2] = -1e30f;
                            if (ng + 1 > r1g) sf[rf][j][3] = -1e30f;
                        }
                    }
                }

                uint32_t pa[2][4][4];
#pragma unroll
                for (int rf = 0; rf < 2; rf++) {
                    float rmax0 = -1e30f, rmax1 = -1e30f;
#pragma unroll
                    for (int j = 0; j < 8; j++) {
                        rmax0 = fmaxf(rmax0, fmaxf(sf[rf][j][0], sf[rf][j][1]));
                        rmax1 = fmaxf(rmax1, fmaxf(sf[rf][j][2], sf[rf][j][3]));
                    }
#pragma unroll
                    for (int off = 1; off <= 2; off <<= 1) {
                        rmax0 = fmaxf(rmax0, __shfl_xor_sync(0xffffffffu, rmax0, off));
                        rmax1 = fmaxf(rmax1, __shfl_xor_sync(0xffffffffu, rmax1, off));
                    }
                    float mn0 = fmaxf(mrow[rf][0], rmax0);
                    float mn1 = fmaxf(mrow[rf][1], rmax1);
                    float corr0 = exp2f(mrow[rf][0] - mn0);
                    float corr1 = exp2f(mrow[rf][1] - mn1);
                    mrow[rf][0] = mn0; mrow[rf][1] = mn1;

#pragma unroll
                    for (int j = 0; j < 8; j++) {
                        uint32_t u0 = exp2h2(sf[rf][j][0] - mn0, sf[rf][j][1] - mn0);
                        uint32_t u1 = exp2h2(sf[rf][j][2] - mn1, sf[rf][j][3] - mn1);
                        pa[rf][j >> 1][(j & 1) * 2 + 0] = u0;
                        pa[rf][j >> 1][(j & 1) * 2 + 1] = u1;
                    }

                    float lacc[4] = {0.f, 0.f, 0.f, 0.f};
#pragma unroll
                    for (int t = 0; t < 4; t++)
                        mma16816(lacc, pa[rf][t], HONES, HONES);
                    lrow[rf][0] = lrow[rf][0] * corr0 + lacc[0];
                    lrow[rf][1] = lrow[rf][1] * corr1 + lacc[2];

#pragma unroll
                    for (int j = 0; j < 8; j++) {
                        of[rf][j][0] *= corr0; of[rf][j][1] *= corr0;
                        of[rf][j][2] *= corr1; of[rf][j][3] *= corr1;
                    }
                }

#pragma unroll
                for (int j2 = 0; j2 < 8; j2++) {
#pragma unroll
                    for (int s2 = 0; s2 < 2; s2++) {
                        uint32_t vf[4];
                        ldm_x4_trans(vf, smem_u32(&Vs[s][32 * s2 + lane][8 * j2]));
#pragma unroll
                        for (int rf = 0; rf < 2; rf++) {
                            mma16816(of[rf][j2], pa[rf][2 * s2],     vf[0], vf[1]);
                            mma16816(of[rf][j2], pa[rf][2 * s2 + 1], vf[2], vf[3]);
                        }
                    }
                }
            }
            __syncthreads();
        }

        if (!split) {
#pragma unroll
            for (int rf = 0; rf < 2; rf++) {
                float inv0 = 1.f / lrow[rf][0], inv1 = 1.f / lrow[rf][1];
                int r0 = gm0 + rf * 16 + (lane >> 2), r1 = r0 + 8;
#pragma unroll
                for (int j2 = 0; j2 < 8; j2++) {
                    int cc = hcol + 8 * j2 + 2 * (lane & 3);
                    *(__half2*)&Ch[(size_t)r0 * DMODEL + cc] =
                        __floats2half2_rn(of[rf][j2][0] * inv0, of[rf][j2][1] * inv0);
                    *(__half2*)&Ch[(size_t)r1 * DMODEL + cc] =
                        __floats2half2_rn(of[rf][j2][2] * inv1, of[rf][j2][3] * inv1);
                }
            }
        } else {
            float* Op = g_Opart[part];
            float2* mlp = g_ml[part];
#pragma unroll
            for (int rf = 0; rf < 2; rf++) {
                int r0 = gm0 + rf * 16 + (lane >> 2), r1 = r0 + 8;
                int p0 = r0 - 2048, p1 = r1 - 2048;
#pragma unroll
                for (int j2 = 0; j2 < 8; j2++) {
                    int cc = hcol + 8 * j2 + 2 * (lane & 3);
                    *(float2*)&Op[(size_t)p0 * DMODEL + cc] =
                        make_float2(of[rf][j2][0], of[rf][j2][1]);
                    *(float2*)&Op[(size_t)p1 * DMODEL + cc] =
                        make_float2(of[rf][j2][2], of[rf][j2][3]);
                }
                if ((lane & 3) == 0) {
                    mlp[p0 * NHEAD + h] = make_float2(mrow[rf][0], lrow[rf][0]);
                    mlp[p1 * NHEAD + h] = make_float2(mrow[rf][1], lrow[rf][1]);
                }
            }
        }
    }
}

// ---------------------------------------------------------------------------
// Combine split-K partials for heavy rows -> Ch[2048..4095] (float4-wide)
// ---------------------------------------------------------------------------
__global__ __launch_bounds__(256) void attn_combine(__half* __restrict__ Ch)
{
    int idx = blockIdx.x * 256 + threadIdx.x;     // one float4 (4 cols) each
    int row = idx >> 8;                            // / 256
    int c4  = idx & 255;                           // float4 index; col = c4*4
    int h   = c4 >> 4;                             // (c4*4)/64

    float2 ml0 = g_ml[0][row * NHEAD + h];
    float2 ml1 = g_ml[1][row * NHEAD + h];
    float m  = fmaxf(ml0.x, ml1.x);
    float f0 = exp2f(ml0.x - m), f1 = exp2f(ml1.x - m);
    float inv = 1.f / (ml0.y * f0 + ml1.y * f1);

    float4 o0 = *(const float4*)&g_Opart[0][(size_t)row * DMODEL + c4 * 4];
    float4 o1 = *(const float4*)&g_Opart[1][(size_t)row * DMODEL + c4 * 4];
    __half2 h0 = __floats2half2_rn((o0.x * f0 + o1.x * f1) * inv,
                                   (o0.y * f0 + o1.y * f1) * inv);
    __half2 h1 = __floats2half2_rn((o0.z * f0 + o1.z * f1) * inv,
                                   (o0.w * f0 + o1.w * f1) * inv);
    uint2 pack;
    pack.x = *reinterpret_cast<uint32_t*>(&h0);
    pack.y = *reinterpret_cast<uint32_t*>(&h1);
    *(uint2*)&Ch[(size_t)(2048 + row) * DMODEL + c4 * 4] = pack;
}

// ---------------------------------------------------------------------------
extern "C" void kernel_launch(void* const* d_in, const int* in_sizes, int n_in,
                              void* d_out, int out_size)
{
    const float* x  = (const float*)d_in[0];
    const float* Wq = (const float*)d_in[1];
    const float* Wk = (const float*)d_in[2];
    const float* Wv = (const float*)d_in[3];
    const float* Wo = (const float*)d_in[4];
    const float* bo = (const float*)d_in[5];
    float* out = (float*)d_out;

    __half *xh, *Qh, *Kh, *Vh, *Chp, *WqT, *WkT, *WvT, *WoT;
    cudaGetSymbolAddress((void**)&xh,  g_xh);
    cudaGetSymbolAddress((void**)&Qh,  g_Qh);
    cudaGetSymbolAddress((void**)&Kh,  g_Kh);
    cudaGetSymbolAddress((void**)&Vh,  g_Vh);
    cudaGetSymbolAddress((void**)&Chp, g_Ch);
    cudaGetSymbolAddress((void**)&WqT, g_WqT);
    cudaGetSymbolAddress((void**)&WkT, g_WkT);
    cudaGetSymbolAddress((void**)&WvT, g_WvT);
    cudaGetSymbolAddress((void**)&WoT, g_WoT);

    f2h_kernel<<<SEQ * DMODEL / 1024, 256>>>(x, xh, SEQ * DMODEL);

    TW4 tw;
    tw.src[0] = Wq;  tw.dst[0] = WqT; tw.scl[0] = 0.125f * 1.44269504089f;
    tw.src[1] = Wk;  tw.dst[1] = WkT; tw.scl[1] = 1.0f;
    tw.src[2] = Wv;  tw.dst[2] = WvT; tw.scl[2] = 1.0f;
    tw.src[3] = Wo;  tw.dst[3] = WoT; tw.scl[3] = 1.0f;
    transW4_kernel<<<dim3(32, 32, 4), dim3(32, 8)>>>(tw);

    const int gsmem  = 3 * 128 * BKP * 2 * (int)sizeof(__half);   // 61,440 B (QKV)
    const int gsmem4 = 4 * 128 * BKP * 2 * (int)sizeof(__half);   // 81,920 B (out)
    cudaFuncSetAttribute(gemm_qkv, cudaFuncAttributeMaxDynamicSharedMemorySize, gsmem);
    cudaFuncSetAttribute(gemm_out, cudaFuncAttributeMaxDynamicSharedMemorySize, gsmem4);

    QKVArgs qa;
    qa.Wt[0] = WqT; qa.Out[0] = Qh;
    qa.Wt[1] = WkT; qa.Out[1] = Kh;
    qa.Wt[2] = WvT; qa.Out[2] = Vh;
    gemm_qkv<<<dim3(DMODEL / 128, SEQ / 128, 3), 128, gsmem>>>(xh, qa);

    const int asmem = (128 + 4 * 64) * APITCH * (int)sizeof(__half) + 16;  // 55,312 B
    cudaFuncSetAttribute(attn_mma, cudaFuncAttributeMaxDynamicSharedMemorySize, asmem);
    attn_mma<<<dim3(444), 128, asmem>>>(Qh, Kh, Vh, Chp);

    attn_combine<<<(2048 * 256) / 256, 256>>>(Chp);

    gemm_out<<<dim3(DMODEL / 128, SEQ / 128), 128, gsmem4>>>(Chp, WoT, bo, out);
}